// round 13
// baseline (speedup 1.0000x reference)
#include <cuda_runtime.h>
#include <cstdint>

#define SEQ 16384
#define EMBD 50
#define HID 300
#define G4 1200
#define NTAG 20
#define START_TAG 18
#define STOP_TAG 19
#define NEGV -10000.0f

// ---------------- scratch (static device globals; no allocation) ----------------
__device__ float d_xg[2][SEQ][G4];                     // input projections (bwd stored time-reversed)
__device__ float d_hout[2][SEQ][HID];                  // hf[s], hb[s] (bwd stored un-reversed)
__device__ __align__(16) float d_feats[SEQ][NTAG];
__device__ __align__(16) unsigned char d_bp[SEQ * NTAG];
__device__ int d_best;

#define VNC 32
#define VCHK (SEQ / VNC)     // 512
__device__ unsigned char d_map[VNC * NTAG];
__device__ unsigned char d_endtag[VNC];

// ---------------- dummy kernels: shift k_lstm into ncu's profiled launch slot ----------------
__global__ void k_nop1() {}
__global__ void k_nop2() {}

// ---------------- kernel 1: embedding + input projection (32 tokens/block) ----------------
#define TPB_E 256
#define TOKB 32
__global__ void k_embed_proj(const int* __restrict__ sent, const float* __restrict__ embed,
                             const float* __restrict__ wf, const float* __restrict__ bfi,
                             const float* __restrict__ bfh,
                             const float* __restrict__ wb, const float* __restrict__ bbi,
                             const float* __restrict__ bbh)
{
    int s0 = blockIdx.x * TOKB;
    __shared__ int toks[TOKB];
    __shared__ float e[TOKB][EMBD];
    int tid = threadIdx.x;
    if (tid < TOKB) toks[tid] = sent[s0 + tid];
    __syncthreads();
    for (int i = tid; i < TOKB * EMBD; i += TPB_E) {
        int u = i / EMBD, k = i - u * EMBD;
        e[u][k] = embed[(size_t)toks[u] * EMBD + k];
    }
    __syncthreads();
    for (int j = tid; j < 2 * G4; j += TPB_E) {
        bool isF = j < G4;
        int jj = isF ? j : j - G4;
        const float* w = (isF ? wf : wb) + (size_t)jj * EMBD;
        float wr[EMBD];
#pragma unroll
        for (int k = 0; k < EMBD; k++) wr[k] = __ldg(&w[k]);
        float b = isF ? (bfi[jj] + bfh[jj]) : (bbi[jj] + bbh[jj]);
#pragma unroll 4
        for (int u = 0; u < TOKB; u++) {
            float acc = b;
#pragma unroll
            for (int k = 0; k < EMBD; k++) acc = fmaf(e[u][k], wr[k], acc);
            int s = s0 + u;
            if (isF) d_xg[0][s][jj] = acc;
            else     d_xg[1][SEQ - 1 - s][jj] = acc;   // bwd step t consumes emb[SEQ-1-t]
        }
    }
}

// ---------------- FMA-only activations (no MUFU; ~1e-7 rel) ----------------
__device__ __forceinline__ float fexp2i(float y) {   // 2^y
    y = fminf(fmaxf(y, -100.0f), 100.0f);
    float z = y + 12582912.0f;
    int ni = __float_as_int(z) - 0x4B400000;
    float f = y - (z - 12582912.0f);
    float p = 1.5403530e-4f;
    p = fmaf(p, f, 1.3333558e-3f);
    p = fmaf(p, f, 9.6181291e-3f);
    p = fmaf(p, f, 5.5504109e-2f);
    p = fmaf(p, f, 2.4022651e-1f);
    p = fmaf(p, f, 6.9314718e-1f);
    p = fmaf(p, f, 1.0f);
    return __int_as_float(__float_as_int(p) + (ni << 23));
}
__device__ __forceinline__ float frcpp(float d) {
    float r = __int_as_float(0x7EF311C3 - __float_as_int(d));
    r = r * (2.0f - d * r);
    r = r * (2.0f - d * r);
    r = r * (2.0f - d * r);
    return r;
}
__device__ __forceinline__ float fsigm(float x) {
    return frcpp(1.0f + fexp2i(-1.4426950409f * x));
}
__device__ __forceinline__ float ftanh(float x) {
    return fmaf(-2.0f, frcpp(1.0f + fexp2i(2.8853900818f * x)), 1.0f);
}

// ---------------- kernel 2: CHUNKED cluster LSTM, 4 streams, shuffle-fused epilogue ----------------
#define NSTR 4
#define CHKL 456
#define WARM 64
#define CELLS_PER 38
#define ROWS_PER 152
#define KCH 100
#define NPAIR 50
#define MV_THREADS 456
#define TPB_L 480
#define HPAD 304
#define PACCP 160
#define NROWS_ALL (NSTR * ROWS_PER)   // 608

__device__ __forceinline__ int q_wstart(int q) { return q * CHKL; }
__device__ __forceinline__ int q_tend(int q)   { return min(q * CHKL + CHKL, SEQ); }
__device__ __forceinline__ int q_s0(int q)     { return q * CHKL - (q ? WARM : 0); }
__device__ __forceinline__ int q_nst(int q)    { return q_tend(q) - q_s0(q); }

__global__ void __launch_bounds__(TPB_L, 1)
k_lstm(const float* __restrict__ whh_f, const float* __restrict__ whh_b,
       const float* __restrict__ h0, const float* __restrict__ c0in)
{
    __shared__ __align__(16) float h_s[NSTR * 2 * HPAD];
    __shared__ __align__(16) float pacc[NSTR * 3 * PACCP];

    int tid  = threadIdx.x;
    int rank = blockIdx.x & 7;
    int cid  = blockIdx.x >> 3;
    int dir  = (cid >= 9) ? 1 : 0;
    int qb   = (cid - dir * 9) * NSTR;
    int cbase = rank * CELLS_PER;
    const float* whh = dir ? whh_b : whh_f;
    const float* xgb = &d_xg[dir][0][0];

    int nstmax = 0;
#pragma unroll
    for (int s = 0; s < NSTR; s++) nstmax = max(nstmax, q_nst(qb + s));

    // ---- matvec thread mapping: tid = kchunk*152 + row ----
    int kchunk = tid / ROWS_PER;
    int row    = tid - kchunk * ROWS_PER;
    int mcell = row >> 2, mgate = row & 3;
    int mgc   = cbase + mcell;
    bool mv   = (tid < MV_THREADS) && (mgc < HID);

    // ---- weights into registers as packed f32 pairs ----
    unsigned long long wp[NPAIR];
    {
        const float* wsrc = whh + (mv ? ((size_t)(mgate * HID + mgc) * HID + kchunk * KCH) : 0);
#pragma unroll
        for (int i = 0; i < NPAIR; i++) {
            float w0 = mv ? __ldg(&wsrc[2 * i])     : 0.0f;
            float w1 = mv ? __ldg(&wsrc[2 * i + 1]) : 0.0f;
            wp[i] = (unsigned long long)__float_as_uint(w0) |
                    ((unsigned long long)__float_as_uint(w1) << 32);
        }
    }

    // ---- init h (both buffers per stream), pacc ----
    for (int k = tid; k < NSTR * 2 * HPAD; k += TPB_L) {
        int kk = k % HPAD;
        int s  = k / (2 * HPAD);
        h_s[k] = ((qb + s) == 0 && kk < HID) ? h0[dir * HID + kk] : 0.0f;
    }
    for (int k = tid; k < NSTR * 3 * PACCP; k += TPB_L) pacc[k] = 0.0f;

    // ---- epilogue roles: pass1 fi0 = tid (streams f0s), pass2 fi1 = tid+480 (stream 3) ----
    int fi0 = tid, fi1 = tid + TPB_L;
    int f0s = fi0 / ROWS_PER, f0r = fi0 - f0s * ROWS_PER;
    bool p2 = (fi1 < NROWS_ALL);                     // tid < 128
    int f1s = 3, f1r = p2 ? (fi1 - f1s * ROWS_PER) : 0;
    bool pf0 = (cbase + (f0r >> 2) < HID);
    bool pf1 = p2 && (cbase + (f1r >> 2) < HID);

    // combine-owner constants, pass1 quad (stream f0s, cell f0r>>2)
    int cm0_gc = cbase + (f0r >> 2);
    int q0 = qb + f0s;
    int cm0_wstart = q_wstart(q0), cm0_tend = q_tend(q0);
    int cm0_s0 = q_s0(q0), cm0_nst = cm0_tend - cm0_s0;
    // pass2 quad (stream 3, cell f1r>>2)
    int cm1_gc = cbase + (f1r >> 2);
    int q1 = qb + 3;
    int cm1_wstart = q_wstart(q1), cm1_tend = q_tend(q1);
    int cm1_s0 = q_s0(q1), cm1_nst = cm1_tend - cm1_s0;

    float creg0 = 0.0f, creg1 = 0.0f;
    if ((tid & 3) == 0 && q0 == 0 && cm0_gc < HID) creg0 = c0in[dir * HID + cm0_gc];
    if (p2 && (tid & 3) == 0 && q1 == 0 && cm1_gc < HID) creg1 = c0in[dir * HID + cm1_gc];

    // xg prefetch (one step ahead; fixed rows per thread)
    int nst0 = q_nst(qb + f0s);
    int nst1 = q_nst(q1);
    const float* p0 = xgb + ((size_t)q_s0(qb + f0s) * G4 + (f0r & 3) * HID + cbase + (f0r >> 2));
    const float* p1 = xgb + ((size_t)q_s0(q1) * G4 + (f1r & 3) * HID + cbase + (f1r >> 2));
    float xn0 = pf0 ? __ldg(p0) : 0.0f;
    float xn1 = pf1 ? __ldg(p1) : 0.0f;

    __syncthreads();
    asm volatile("barrier.cluster.arrive.aligned;" ::: "memory");
    asm volatile("barrier.cluster.wait.aligned;" ::: "memory");

    unsigned int h_smem_base = (unsigned int)__cvta_generic_to_shared(h_s);

    for (int lt = 0; lt < nstmax; lt++) {
        float xv0 = xn0, xv1 = xn1;
        if (pf0 && lt + 1 < nst0) xn0 = __ldg(p0 += G4);
        if (pf1 && lt + 1 < nst1) xn1 = __ldg(p1 += G4);

        // batched matvec: register weights, 4 h-streams (broadcast LDS.128)
        if (tid < MV_THREADS) {
#pragma unroll
            for (int s = 0; s < NSTR; s++) {
                const ulonglong2* hb =
                    (const ulonglong2*)(h_s + (s * 2 + (lt & 1)) * HPAD + kchunk * KCH);
                unsigned long long a0 = 0ull, a1 = 0ull;
#pragma unroll
                for (int i = 0; i < NPAIR / 2; i++) {
                    ulonglong2 hp = hb[i];
                    asm("fma.rn.f32x2 %0, %1, %2, %0;" : "+l"(a0) : "l"(wp[2 * i]),     "l"(hp.x));
                    asm("fma.rn.f32x2 %0, %1, %2, %0;" : "+l"(a1) : "l"(wp[2 * i + 1]), "l"(hp.y));
                }
                float q0v = __uint_as_float((unsigned int)a0) + __uint_as_float((unsigned int)(a0 >> 32));
                float q1v = __uint_as_float((unsigned int)a1) + __uint_as_float((unsigned int)(a1 >> 32));
                pacc[(s * 3 + kchunk) * PACCP + row] = q0v + q1v;
            }
        }
        __syncthreads();

        // ---- fused epilogue pass 1: all 480 threads (rows fi0 = 0..479) ----
        {
            int pb = f0s * 3 * PACCP + f0r;
            float g = xv0 + pacc[pb] + pacc[pb + PACCP] + pacc[pb + 2 * PACCP];
            float a = ((f0r & 3) == 2) ? ftanh(g) : fsigm(g);
            int lb = (tid & 31) & ~3;
            float ai = __shfl_sync(0xffffffffu, a, lb + 0);
            float af = __shfl_sync(0xffffffffu, a, lb + 1);
            float ag = __shfl_sync(0xffffffffu, a, lb + 2);
            float ao = __shfl_sync(0xffffffffu, a, lb + 3);
            if ((tid & 3) == 0 && cm0_gc < HID) {
                creg0 = af * creg0 + ai * ag;
                float hv = ao * ftanh(creg0);
                int t = cm0_s0 + lt;
                if (t >= cm0_wstart && t < cm0_tend) {
                    int pos = dir ? (SEQ - 1 - t) : t;
                    d_hout[dir][pos][cm0_gc] = hv;
                }
                if (lt + 1 < cm0_nst) {
                    unsigned int dst = h_smem_base +
                        (unsigned int)(((f0s * 2 + ((lt + 1) & 1)) * HPAD + cm0_gc) * 4);
#pragma unroll
                    for (int p = 0; p < 8; p++) {
                        unsigned int ra;
                        asm volatile("mapa.shared::cluster.u32 %0, %1, %2;"
                                     : "=r"(ra) : "r"(dst), "r"(p));
                        asm volatile("st.shared::cluster.f32 [%0], %1;"
                                     :: "r"(ra), "f"(hv));
                    }
                }
            }
        }
        // ---- fused epilogue pass 2: tid<128 = 4 full warps (rows fi1 = 480..607, stream 3) ----
        if (p2) {
            int pb = f1s * 3 * PACCP + f1r;
            float g = xv1 + pacc[pb] + pacc[pb + PACCP] + pacc[pb + 2 * PACCP];
            float a = ((f1r & 3) == 2) ? ftanh(g) : fsigm(g);
            int lb = (tid & 31) & ~3;
            float ai = __shfl_sync(0xffffffffu, a, lb + 0);
            float af = __shfl_sync(0xffffffffu, a, lb + 1);
            float ag = __shfl_sync(0xffffffffu, a, lb + 2);
            float ao = __shfl_sync(0xffffffffu, a, lb + 3);
            if ((tid & 3) == 0 && cm1_gc < HID) {
                creg1 = af * creg1 + ai * ag;
                float hv = ao * ftanh(creg1);
                int t = cm1_s0 + lt;
                if (t >= cm1_wstart && t < cm1_tend) {
                    int pos = dir ? (SEQ - 1 - t) : t;
                    d_hout[dir][pos][cm1_gc] = hv;
                }
                if (lt + 1 < cm1_nst) {
                    unsigned int dst = h_smem_base +
                        (unsigned int)(((3 * 2 + ((lt + 1) & 1)) * HPAD + cm1_gc) * 4);
#pragma unroll
                    for (int p = 0; p < 8; p++) {
                        unsigned int ra;
                        asm volatile("mapa.shared::cluster.u32 %0, %1, %2;"
                                     : "=r"(ra) : "r"(dst), "r"(p));
                        asm volatile("st.shared::cluster.f32 [%0], %1;"
                                     :: "r"(ra), "f"(hv));
                    }
                }
            }
        }
        asm volatile("barrier.cluster.arrive.aligned;" ::: "memory");
        asm volatile("barrier.cluster.wait.aligned;" ::: "memory");
    }
}

// ---------------- kernel 3: tag projection, 8 tokens/block ----------------
#define FTOK 8
__global__ void k_feats(const float* __restrict__ wtag, const float* __restrict__ btag)
{
    int sb = blockIdx.x * FTOK;
    __shared__ float hbuf[FTOK][2 * HID];
    int tid = threadIdx.x, warp = tid >> 5, lane = tid & 31;
    for (int i = tid; i < FTOK * 2 * HID; i += blockDim.x) {
        int u = i / (2 * HID), kk = i - u * 2 * HID;
        hbuf[u][kk] = (kk < HID) ? d_hout[0][sb + u][kk] : d_hout[1][sb + u][kk - HID];
    }
    __syncthreads();
    if (warp < NTAG) {
        const float* w = wtag + warp * 2 * HID;
        float wr[19];
#pragma unroll
        for (int i = 0; i < 19; i++) {
            int kk = lane + 32 * i;
            wr[i] = (kk < 2 * HID) ? __ldg(&w[kk]) : 0.0f;
        }
        float bt = btag[warp];
        for (int u = 0; u < FTOK; u++) {
            float acc = 0.0f;
#pragma unroll
            for (int i = 0; i < 19; i++) {
                int kk = lane + 32 * i;
                if (kk < 2 * HID) acc = fmaf(hbuf[u][kk], wr[i], acc);
            }
#pragma unroll
            for (int o = 16; o; o >>= 1) acc += __shfl_down_sync(0xffffffffu, acc, o);
            if (lane == 0) d_feats[sb + u][warp] = acc + bt;
        }
    }
}

// ---------------- kernel 4: exact serial Viterbi forward ----------------
#define VCH 512
#define VIT_SMEM_BYTES (2 * VCH * NTAG * 4)
__global__ void k_viterbi(const float* __restrict__ trans, float* out, int out_size)
{
    extern __shared__ float fb[];   // [2][VCH*NTAG] staged feats
    int tid = threadIdx.x;
    int lane = tid & 31;

    if (tid >= 32) {   // preload chunk 0
        const float4* src = (const float4*)&d_feats[0][0];
        float4* dst = (float4*)fb;
        for (int i = tid - 32; i < VCH * NTAG / 4; i += (int)blockDim.x - 32) dst[i] = src[i];
    }
    __syncthreads();

    float fv = -3.4e38f;
    float trow[NTAG];
    if (tid < 32) {
        if (lane < NTAG) {
            fv = (lane == START_TAG) ? 0.0f : NEGV;
#pragma unroll
            for (int p = 0; p < NTAG; p++) trow[p] = __ldg(&trans[lane * NTAG + p]);
        } else {
#pragma unroll
            for (int p = 0; p < NTAG; p++) trow[p] = 0.0f;
        }
    }

    const int nch = SEQ / VCH;
    for (int c = 0; c < nch; c++) {
        if (tid >= 32) {
            if (c + 1 < nch) {
                const float4* src = (const float4*)&d_feats[(c + 1) * VCH][0];
                float4* dst = (float4*)(fb + ((c + 1) & 1) * VCH * NTAG);
                for (int i = tid - 32; i < VCH * NTAG / 4; i += (int)blockDim.x - 32) dst[i] = src[i];
            }
        } else {
            const float* fbase = fb + (c & 1) * VCH * NTAG;
            int lsafe = (lane < NTAG) ? lane : 0;
            for (int j = 0; j < VCH; j++) {
                float fcur = fbase[j * NTAG + lsafe];
                float v[NTAG];
#pragma unroll
                for (int p = 0; p < NTAG; p++)
                    v[p] = __shfl_sync(0xffffffffu, fv, p) + trow[p];
                float m0 = fmaxf(v[0], v[1]),   m1 = fmaxf(v[2], v[3]);
                float m2 = fmaxf(v[4], v[5]),   m3 = fmaxf(v[6], v[7]);
                float m4 = fmaxf(v[8], v[9]),   m5 = fmaxf(v[10], v[11]);
                float m6 = fmaxf(v[12], v[13]), m7 = fmaxf(v[14], v[15]);
                float m8 = fmaxf(v[16], v[17]), m9 = fmaxf(v[18], v[19]);
                float n0 = fmaxf(m0, m1), n1 = fmaxf(m2, m3);
                float n2 = fmaxf(m4, m5), n3 = fmaxf(m6, m7), n4 = fmaxf(m8, m9);
                float best = fmaxf(fmaxf(fmaxf(n0, n1), fmaxf(n2, n3)), n4);
                unsigned msk = 0;
#pragma unroll
                for (int p = 0; p < NTAG; p++)
                    msk |= (v[p] == best) ? (1u << p) : 0u;
                int bi = __ffs(msk) - 1;   // first max == jnp.argmax
                if (lane < NTAG) {
                    d_bp[(size_t)(c * VCH + j) * NTAG + lane] = (unsigned char)bi;
                    fv = best + fcur;
                }
            }
        }
        __syncthreads();
    }

    if (tid < 32) {
        float term = (lane < NTAG) ? (fv + __ldg(&trans[STOP_TAG * NTAG + lane])) : -3.4e38f;
        float best = -3.4e38f; int bi = 0;
#pragma unroll
        for (int p = 0; p < NTAG; p++) {
            float v = __shfl_sync(0xffffffffu, term, p);
            if (v > best) { best = v; bi = p; }
        }
        if (lane == 0) {
            d_best = bi;
            if (out_size > SEQ) out[0] = best;   // exact score
        }
    }
}

// ---------------- kernel 5a: per-chunk end->start tag maps (integer exact) ----------------
__global__ void k_map()
{
    __shared__ unsigned char bps[VCHK * NTAG];
    int k = blockIdx.x, tid = threadIdx.x;
    {
        const uint4* src = (const uint4*)&d_bp[(size_t)k * VCHK * NTAG];
        uint4* dst = (uint4*)bps;
        for (int i = tid; i < VCHK * NTAG / 16; i += blockDim.x) dst[i] = src[i];
    }
    __syncthreads();
    if (tid < NTAG) {
        int tg = tid;
        for (int j = VCHK - 1; j >= 0; j--) tg = bps[j * NTAG + tg];
        d_map[k * NTAG + tid] = (unsigned char)tg;
    }
}

// ---------------- kernel 5b: chain chunk end-tags ----------------
__global__ void k_chain()
{
    if (threadIdx.x == 0) {
        int e = d_best;
        for (int k = VNC - 1; k >= 0; k--) {
            d_endtag[k] = (unsigned char)e;
            e = d_map[k * NTAG + e];
        }
    }
}

// ---------------- kernel 5c: per-chunk path emission ----------------
__global__ void k_emit(float* out, int out_size)
{
    __shared__ unsigned char bps[VCHK * NTAG];
    __shared__ unsigned char ys[VCHK];
    int k = blockIdx.x, tid = threadIdx.x;
    int a = k * VCHK;
    {
        const uint4* src = (const uint4*)&d_bp[(size_t)a * NTAG];
        uint4* dst = (uint4*)bps;
        for (int i = tid; i < VCHK * NTAG / 16; i += blockDim.x) dst[i] = src[i];
    }
    __syncthreads();
    if (tid == 0) {
        int tg = d_endtag[k];
        for (int j = VCHK - 1; j >= 0; j--) { ys[j] = (unsigned char)tg; tg = bps[j * NTAG + tg]; }
    }
    __syncthreads();
    int off = (out_size > SEQ) ? (out_size - SEQ) : 0;
    for (int idx = tid; idx < VCHK; idx += blockDim.x)
        out[off + a + idx] = (float)ys[idx];
}

// ---------------- launch ----------------
extern "C" void kernel_launch(void* const* d_in, const int* in_sizes, int n_in,
                              void* d_out, int out_size)
{
    const int*   sent  = (const int*)d_in[0];
    const float* embed = (const float*)d_in[1];
    const float* wihf  = (const float*)d_in[2];
    const float* whhf  = (const float*)d_in[3];
    const float* bihf  = (const float*)d_in[4];
    const float* bhhf  = (const float*)d_in[5];
    const float* wihb  = (const float*)d_in[6];
    const float* whhb  = (const float*)d_in[7];
    const float* bihb  = (const float*)d_in[8];
    const float* bhhb  = (const float*)d_in[9];
    const float* h0    = (const float*)d_in[10];
    const float* c0    = (const float*)d_in[11];
    const float* wtag  = (const float*)d_in[12];
    const float* btag  = (const float*)d_in[13];
    const float* trans = (const float*)d_in[14];
    float* out = (float*)d_out;

    cudaFuncSetAttribute(k_viterbi, cudaFuncAttributeMaxDynamicSharedMemorySize, VIT_SMEM_BYTES);

    // 1) embedding + input projections
    k_embed_proj<<<SEQ / TOKB, TPB_E>>>(sent, embed, wihf, bihf, bhhf, wihb, bihb, bhhb);

    // 1b) no-op shims: place k_lstm in the launch slot ncu's fixed -s window captures
    k_nop1<<<1, 32>>>();
    k_nop2<<<1, 32>>>();

    // 2) chunked BiLSTM: 18 clusters of 8 CTAs, 4 chunk-streams per cluster
    {
        cudaLaunchConfig_t cfg = {};
        cfg.gridDim = dim3(144, 1, 1);
        cfg.blockDim = dim3(TPB_L, 1, 1);
        cfg.dynamicSmemBytes = 0;
        cfg.stream = 0;
        cudaLaunchAttribute attrs[1];
        attrs[0].id = cudaLaunchAttributeClusterDimension;
        attrs[0].val.clusterDim.x = 8;
        attrs[0].val.clusterDim.y = 1;
        attrs[0].val.clusterDim.z = 1;
        cfg.attrs = attrs;
        cfg.numAttrs = 1;
        cudaLaunchKernelEx(&cfg, k_lstm, whhf, whhb, h0, c0);
    }

    // 3) tag projection (8 tokens/block)
    k_feats<<<SEQ / FTOK, 640>>>(wtag, btag);

    // 4) exact serial Viterbi forward (bps + best + score)
    k_viterbi<<<1, 256, VIT_SMEM_BYTES>>>(trans, out, out_size);

    // 5) exact parallel backtrace: chunk maps -> chain -> emit
    k_map<<<VNC, 128>>>();
    k_chain<<<1, 32>>>();
    k_emit<<<VNC, 128>>>(out, out_size);
}

// round 14
// speedup vs baseline: 1.5142x; 1.5142x over previous
#include <cuda_runtime.h>
#include <cstdint>

#define SEQ 16384
#define EMBD 50
#define HID 300
#define G4 1200
#define NTAG 20
#define START_TAG 18
#define STOP_TAG 19
#define NEGV -10000.0f

// ---------------- scratch (static device globals; no allocation) ----------------
__device__ float d_xg[2][SEQ][G4];                     // input projections (bwd stored time-reversed)
__device__ float d_hout[2][SEQ][HID];                  // hf[s], hb[s] (bwd stored un-reversed)
__device__ __align__(16) float d_feats[SEQ][NTAG];
__device__ __align__(16) float d_fv[SEQ][NTAG];        // fv entering step t (pre-feat state)
__device__ __align__(16) unsigned char d_bp[SEQ * NTAG];
__device__ int d_best;

#define VNC 32
#define VCHK (SEQ / VNC)     // 512
__device__ unsigned char d_map[VNC * NTAG];
__device__ unsigned char d_endtag[VNC];

// ---------------- dummy kernels: keep k_lstm in ncu's profiled launch slot ----------------
__global__ void k_nop1() {}
__global__ void k_nop2() {}

// ---------------- kernel 1: embedding + input projection (32 tokens/block) ----------------
#define TPB_E 256
#define TOKB 32
__global__ void k_embed_proj(const int* __restrict__ sent, const float* __restrict__ embed,
                             const float* __restrict__ wf, const float* __restrict__ bfi,
                             const float* __restrict__ bfh,
                             const float* __restrict__ wb, const float* __restrict__ bbi,
                             const float* __restrict__ bbh)
{
    int s0 = blockIdx.x * TOKB;
    __shared__ int toks[TOKB];
    __shared__ float e[TOKB][EMBD];
    int tid = threadIdx.x;
    if (tid < TOKB) toks[tid] = sent[s0 + tid];
    __syncthreads();
    for (int i = tid; i < TOKB * EMBD; i += TPB_E) {
        int u = i / EMBD, k = i - u * EMBD;
        e[u][k] = embed[(size_t)toks[u] * EMBD + k];
    }
    __syncthreads();
    for (int j = tid; j < 2 * G4; j += TPB_E) {
        bool isF = j < G4;
        int jj = isF ? j : j - G4;
        const float* w = (isF ? wf : wb) + (size_t)jj * EMBD;
        float wr[EMBD];
#pragma unroll
        for (int k = 0; k < EMBD; k++) wr[k] = __ldg(&w[k]);
        float b = isF ? (bfi[jj] + bfh[jj]) : (bbi[jj] + bbh[jj]);
#pragma unroll 4
        for (int u = 0; u < TOKB; u++) {
            float acc = b;
#pragma unroll
            for (int k = 0; k < EMBD; k++) acc = fmaf(e[u][k], wr[k], acc);
            int s = s0 + u;
            if (isF) d_xg[0][s][jj] = acc;
            else     d_xg[1][SEQ - 1 - s][jj] = acc;   // bwd step t consumes emb[SEQ-1-t]
        }
    }
}

// ---------------- FMA-only activations (no MUFU; ~1e-7 rel) ----------------
__device__ __forceinline__ float fexp2i(float y) {   // 2^y
    y = fminf(fmaxf(y, -100.0f), 100.0f);
    float z = y + 12582912.0f;
    int ni = __float_as_int(z) - 0x4B400000;
    float f = y - (z - 12582912.0f);
    float p = 1.5403530e-4f;
    p = fmaf(p, f, 1.3333558e-3f);
    p = fmaf(p, f, 9.6181291e-3f);
    p = fmaf(p, f, 5.5504109e-2f);
    p = fmaf(p, f, 2.4022651e-1f);
    p = fmaf(p, f, 6.9314718e-1f);
    p = fmaf(p, f, 1.0f);
    return __int_as_float(__float_as_int(p) + (ni << 23));
}
__device__ __forceinline__ float frcpp(float d) {
    float r = __int_as_float(0x7EF311C3 - __float_as_int(d));
    r = r * (2.0f - d * r);
    r = r * (2.0f - d * r);
    r = r * (2.0f - d * r);
    return r;
}
__device__ __forceinline__ float fsigm(float x) {
    return frcpp(1.0f + fexp2i(-1.4426950409f * x));
}
__device__ __forceinline__ float ftanh(float x) {
    return fmaf(-2.0f, frcpp(1.0f + fexp2i(2.8853900818f * x)), 1.0f);
}

// ---------------- kernel 2: CHUNKED cluster LSTM (R12 version, best known) ----------------
#define NSTR 4
#define CHKL 456
#define WARM 64
#define CELLS_PER 38
#define ROWS_PER 152
#define KCH 100
#define NPAIR 50
#define MV_THREADS 456
#define TPB_L 480
#define HPAD 304
#define PACCP 160
#define NROWS_ALL (NSTR * ROWS_PER)

__device__ __forceinline__ int q_wstart(int q) { return q * CHKL; }
__device__ __forceinline__ int q_tend(int q)   { return min(q * CHKL + CHKL, SEQ); }
__device__ __forceinline__ int q_s0(int q)     { return q * CHKL - (q ? WARM : 0); }
__device__ __forceinline__ int q_nst(int q)    { return q_tend(q) - q_s0(q); }

__global__ void __launch_bounds__(TPB_L, 1)
k_lstm(const float* __restrict__ whh_f, const float* __restrict__ whh_b,
       const float* __restrict__ h0, const float* __restrict__ c0in)
{
    __shared__ __align__(16) float h_s[NSTR * 2 * HPAD];
    __shared__ __align__(16) float pacc[NSTR * 3 * PACCP];
    __shared__ __align__(16) float act[NROWS_ALL];

    int tid  = threadIdx.x;
    int rank = blockIdx.x & 7;
    int cid  = blockIdx.x >> 3;
    int dir  = (cid >= 9) ? 1 : 0;
    int qb   = (cid - dir * 9) * NSTR;
    int cbase = rank * CELLS_PER;
    const float* whh = dir ? whh_b : whh_f;
    const float* xgb = &d_xg[dir][0][0];

    int nstmax = 0;
#pragma unroll
    for (int s = 0; s < NSTR; s++) nstmax = max(nstmax, q_nst(qb + s));

    int kchunk = tid / ROWS_PER;
    int row    = tid - kchunk * ROWS_PER;
    int mcell = row >> 2, mgate = row & 3;
    int mgc   = cbase + mcell;
    bool mv   = (tid < MV_THREADS) && (mgc < HID);

    unsigned long long wp[NPAIR];
    {
        const float* wsrc = whh + (mv ? ((size_t)(mgate * HID + mgc) * HID + kchunk * KCH) : 0);
#pragma unroll
        for (int i = 0; i < NPAIR; i++) {
            float w0 = mv ? __ldg(&wsrc[2 * i])     : 0.0f;
            float w1 = mv ? __ldg(&wsrc[2 * i + 1]) : 0.0f;
            wp[i] = (unsigned long long)__float_as_uint(w0) |
                    ((unsigned long long)__float_as_uint(w1) << 32);
        }
    }

    for (int k = tid; k < NSTR * 2 * HPAD; k += TPB_L) {
        int kk = k % HPAD;
        int s  = k / (2 * HPAD);
        h_s[k] = ((qb + s) == 0 && kk < HID) ? h0[dir * HID + kk] : 0.0f;
    }
    for (int k = tid; k < NSTR * 3 * PACCP; k += TPB_L) pacc[k] = 0.0f;

    bool cm = (tid < ROWS_PER);
    int cm_s = tid & 3, cm_cell = tid >> 2;
    int cm_gc = cbase + cm_cell;
    int cm_q = qb + cm_s;
    int cm_wstart = q_wstart(cm_q);
    int cm_tend   = q_tend(cm_q);
    int cm_s0     = q_s0(cm_q);
    int cm_nst    = cm_tend - cm_s0;
    float creg = 0.0f;
    if (cm && cm_q == 0 && cm_gc < HID) creg = c0in[dir * HID + cm_gc];

    int fi0 = tid, fi1 = tid + TPB_L;
    int f0s = fi0 / ROWS_PER, f0r = fi0 - f0s * ROWS_PER;
    int f1s = (fi1 < NROWS_ALL) ? fi1 / ROWS_PER : 0;
    int f1r = (fi1 < NROWS_ALL) ? (fi1 - f1s * ROWS_PER) : 0;
    bool pf0 = (fi0 < NROWS_ALL) && (cbase + (f0r >> 2) < HID);
    bool pf1 = (fi1 < NROWS_ALL) && (cbase + (f1r >> 2) < HID);
    int nst0 = q_nst(qb + f0s);
    int nst1 = q_nst(qb + f1s);
    const float* p0 = xgb + ((size_t)q_s0(qb + f0s) * G4 + (f0r & 3) * HID + cbase + (f0r >> 2));
    const float* p1 = xgb + ((size_t)q_s0(qb + f1s) * G4 + (f1r & 3) * HID + cbase + (f1r >> 2));
    float xn0 = pf0 ? __ldg(p0) : 0.0f;
    float xn1 = pf1 ? __ldg(p1) : 0.0f;

    __syncthreads();
    asm volatile("barrier.cluster.arrive.aligned;" ::: "memory");
    asm volatile("barrier.cluster.wait.aligned;" ::: "memory");

    unsigned int h_smem_base = (unsigned int)__cvta_generic_to_shared(h_s);

    for (int lt = 0; lt < nstmax; lt++) {
        float xv0 = xn0, xv1 = xn1;
        if (pf0 && lt + 1 < nst0) xn0 = __ldg(p0 += G4);
        if (pf1 && lt + 1 < nst1) xn1 = __ldg(p1 += G4);

        if (tid < MV_THREADS) {
#pragma unroll
            for (int s = 0; s < NSTR; s++) {
                const ulonglong2* hb =
                    (const ulonglong2*)(h_s + (s * 2 + (lt & 1)) * HPAD + kchunk * KCH);
                unsigned long long a0 = 0ull, a1 = 0ull;
#pragma unroll
                for (int i = 0; i < NPAIR / 2; i++) {
                    ulonglong2 hp = hb[i];
                    asm("fma.rn.f32x2 %0, %1, %2, %0;" : "+l"(a0) : "l"(wp[2 * i]),     "l"(hp.x));
                    asm("fma.rn.f32x2 %0, %1, %2, %0;" : "+l"(a1) : "l"(wp[2 * i + 1]), "l"(hp.y));
                }
                float q0 = __uint_as_float((unsigned int)a0) + __uint_as_float((unsigned int)(a0 >> 32));
                float q1 = __uint_as_float((unsigned int)a1) + __uint_as_float((unsigned int)(a1 >> 32));
                pacc[(s * 3 + kchunk) * PACCP + row] = q0 + q1;
            }
        }
        __syncthreads();

        {
            int pb0 = f0s * 3 * PACCP + f0r;
            float g0 = xv0 + pacc[pb0] + pacc[pb0 + PACCP] + pacc[pb0 + 2 * PACCP];
            act[fi0] = ((f0r & 3) == 2) ? ftanh(g0) : fsigm(g0);
            if (fi1 < NROWS_ALL) {
                int pb1 = f1s * 3 * PACCP + f1r;
                float g1 = xv1 + pacc[pb1] + pacc[pb1 + PACCP] + pacc[pb1 + 2 * PACCP];
                act[fi1] = ((f1r & 3) == 2) ? ftanh(g1) : fsigm(g1);
            }
        }
        __syncthreads();

        if (cm) {
            float4 av = *(const float4*)&act[cm_s * ROWS_PER + cm_cell * 4];
            creg = av.y * creg + av.x * av.z;
            float hv = av.w * ftanh(creg);
            int t = cm_s0 + lt;
            if (cm_gc < HID) {
                if (t >= cm_wstart && t < cm_tend) {
                    int pos = dir ? (SEQ - 1 - t) : t;
                    d_hout[dir][pos][cm_gc] = hv;
                }
                if (lt + 1 < cm_nst) {
                    unsigned int dst = h_smem_base +
                        (unsigned int)(((cm_s * 2 + ((lt + 1) & 1)) * HPAD + cm_gc) * 4);
#pragma unroll
                    for (int p = 0; p < 8; p++) {
                        unsigned int ra;
                        asm volatile("mapa.shared::cluster.u32 %0, %1, %2;"
                                     : "=r"(ra) : "r"(dst), "r"(p));
                        asm volatile("st.shared::cluster.f32 [%0], %1;"
                                     :: "r"(ra), "f"(hv));
                    }
                }
            }
        }
        asm volatile("barrier.cluster.arrive.aligned;" ::: "memory");
        asm volatile("barrier.cluster.wait.aligned;" ::: "memory");
    }
}

// ---------------- kernel 3: tag projection, 8 tokens/block ----------------
#define FTOK 8
__global__ void k_feats(const float* __restrict__ wtag, const float* __restrict__ btag)
{
    int sb = blockIdx.x * FTOK;
    __shared__ float hbuf[FTOK][2 * HID];
    int tid = threadIdx.x, warp = tid >> 5, lane = tid & 31;
    for (int i = tid; i < FTOK * 2 * HID; i += blockDim.x) {
        int u = i / (2 * HID), kk = i - u * 2 * HID;
        hbuf[u][kk] = (kk < HID) ? d_hout[0][sb + u][kk] : d_hout[1][sb + u][kk - HID];
    }
    __syncthreads();
    if (warp < NTAG) {
        const float* w = wtag + warp * 2 * HID;
        float wr[19];
#pragma unroll
        for (int i = 0; i < 19; i++) {
            int kk = lane + 32 * i;
            wr[i] = (kk < 2 * HID) ? __ldg(&w[kk]) : 0.0f;
        }
        float bt = btag[warp];
        for (int u = 0; u < FTOK; u++) {
            float acc = 0.0f;
#pragma unroll
            for (int i = 0; i < 19; i++) {
                int kk = lane + 32 * i;
                if (kk < 2 * HID) acc = fmaf(hbuf[u][kk], wr[i], acc);
            }
#pragma unroll
            for (int o = 16; o; o >>= 1) acc += __shfl_down_sync(0xffffffffu, acc, o);
            if (lane == 0) d_feats[sb + u][warp] = acc + bt;
        }
    }
}

// ---------------- kernel 4: serial fv recurrence ONLY (stores fv trajectory) ----------------
#define VCH 512
#define VIT_SMEM_BYTES (2 * VCH * NTAG * 4)
__global__ void k_vitfv(const float* __restrict__ trans, float* out, int out_size)
{
    extern __shared__ float fb[];   // [2][VCH*NTAG] staged feats
    int tid = threadIdx.x;
    int lane = tid & 31;

    if (tid >= 32) {   // preload chunk 0
        const float4* src = (const float4*)&d_feats[0][0];
        float4* dst = (float4*)fb;
        for (int i = tid - 32; i < VCH * NTAG / 4; i += (int)blockDim.x - 32) dst[i] = src[i];
    }
    __syncthreads();

    float fv = -3.4e38f;
    float trow[NTAG];
    if (tid < 32) {
        if (lane < NTAG) {
            fv = (lane == START_TAG) ? 0.0f : NEGV;
#pragma unroll
            for (int p = 0; p < NTAG; p++) trow[p] = __ldg(&trans[lane * NTAG + p]);
        } else {
#pragma unroll
            for (int p = 0; p < NTAG; p++) trow[p] = 0.0f;
        }
    }

    const int nch = SEQ / VCH;
    for (int c = 0; c < nch; c++) {
        if (tid >= 32) {
            if (c + 1 < nch) {
                const float4* src = (const float4*)&d_feats[(c + 1) * VCH][0];
                float4* dst = (float4*)(fb + ((c + 1) & 1) * VCH * NTAG);
                for (int i = tid - 32; i < VCH * NTAG / 4; i += (int)blockDim.x - 32) dst[i] = src[i];
            }
        } else {
            const float* fbase = fb + (c & 1) * VCH * NTAG;
            int lsafe = (lane < NTAG) ? lane : 0;
            for (int j = 0; j < VCH; j++) {
                int t = c * VCH + j;
                // record pre-step fv (input state of step t) — fire-and-forget, coalesced 80B
                if (lane < NTAG) d_fv[t][lane] = fv;
                float fcur = fbase[j * NTAG + lsafe];
                float v[NTAG];
#pragma unroll
                for (int p = 0; p < NTAG; p++)
                    v[p] = __shfl_sync(0xffffffffu, fv, p) + trow[p];
                float m0 = fmaxf(v[0], v[1]),   m1 = fmaxf(v[2], v[3]);
                float m2 = fmaxf(v[4], v[5]),   m3 = fmaxf(v[6], v[7]);
                float m4 = fmaxf(v[8], v[9]),   m5 = fmaxf(v[10], v[11]);
                float m6 = fmaxf(v[12], v[13]), m7 = fmaxf(v[14], v[15]);
                float m8 = fmaxf(v[16], v[17]), m9 = fmaxf(v[18], v[19]);
                float n0 = fmaxf(m0, m1), n1 = fmaxf(m2, m3);
                float n2 = fmaxf(m4, m5), n3 = fmaxf(m6, m7), n4 = fmaxf(m8, m9);
                float best = fmaxf(fmaxf(fmaxf(n0, n1), fmaxf(n2, n3)), n4);
                if (lane < NTAG) fv = best + fcur;
            }
        }
        __syncthreads();
    }

    if (tid < 32) {
        float term = (lane < NTAG) ? (fv + __ldg(&trans[STOP_TAG * NTAG + lane])) : -3.4e38f;
        float best = -3.4e38f; int bi = 0;
#pragma unroll
        for (int p = 0; p < NTAG; p++) {
            float v = __shfl_sync(0xffffffffu, term, p);
            if (v > best) { best = v; bi = p; }   // strict > == first-max
        }
        if (lane == 0) {
            d_best = bi;
            if (out_size > SEQ) out[0] = best;   // exact score
        }
    }
}

// ---------------- kernel 4b: parallel backpointers from fv trajectory (bitwise exact) ----------------
#define BPT 16   // steps per block; block = 16*20 = 320 threads
__global__ void k_bp(const float* __restrict__ trans)
{
    __shared__ float fvs[BPT * NTAG];
    __shared__ float tr[NTAG * NTAG];
    int t0 = blockIdx.x * BPT;
    int tid = threadIdx.x;
    for (int i = tid; i < NTAG * NTAG; i += blockDim.x) tr[i] = __ldg(&trans[i]);
    {
        const float4* src = (const float4*)&d_fv[t0][0];
        float4* dst = (float4*)fvs;
        for (int i = tid; i < BPT * NTAG / 4; i += blockDim.x) dst[i] = src[i];
    }
    __syncthreads();
    int j = tid / NTAG, l = tid - (tid / NTAG) * NTAG;
    if (j < BPT) {
        const float* fvr = &fvs[j * NTAG];
        const float* trl = &tr[l * NTAG];
        float best = -3.4e38f; int bi = 0;
#pragma unroll
        for (int p = 0; p < NTAG; p++) {
            float v = fvr[p] + trl[p];
            if (v > best) { best = v; bi = p; }   // strict > == first-max (jnp.argmax)
        }
        d_bp[(size_t)(t0 + j) * NTAG + l] = (unsigned char)bi;
    }
}

// ---------------- kernel 5a: per-chunk end->start tag maps (integer exact) ----------------
__global__ void k_map()
{
    __shared__ unsigned char bps[VCHK * NTAG];
    int k = blockIdx.x, tid = threadIdx.x;
    {
        const uint4* src = (const uint4*)&d_bp[(size_t)k * VCHK * NTAG];
        uint4* dst = (uint4*)bps;
        for (int i = tid; i < VCHK * NTAG / 16; i += blockDim.x) dst[i] = src[i];
    }
    __syncthreads();
    if (tid < NTAG) {
        int tg = tid;
        for (int j = VCHK - 1; j >= 0; j--) tg = bps[j * NTAG + tg];
        d_map[k * NTAG + tid] = (unsigned char)tg;
    }
}

// ---------------- kernel 5b: chain chunk end-tags ----------------
__global__ void k_chain()
{
    if (threadIdx.x == 0) {
        int e = d_best;
        for (int k = VNC - 1; k >= 0; k--) {
            d_endtag[k] = (unsigned char)e;
            e = d_map[k * NTAG + e];
        }
    }
}

// ---------------- kernel 5c: per-chunk path emission ----------------
__global__ void k_emit(float* out, int out_size)
{
    __shared__ unsigned char bps[VCHK * NTAG];
    __shared__ unsigned char ys[VCHK];
    int k = blockIdx.x, tid = threadIdx.x;
    int a = k * VCHK;
    {
        const uint4* src = (const uint4*)&d_bp[(size_t)a * NTAG];
        uint4* dst = (uint4*)bps;
        for (int i = tid; i < VCHK * NTAG / 16; i += blockDim.x) dst[i] = src[i];
    }
    __syncthreads();
    if (tid == 0) {
        int tg = d_endtag[k];
        for (int j = VCHK - 1; j >= 0; j--) { ys[j] = (unsigned char)tg; tg = bps[j * NTAG + tg]; }
    }
    __syncthreads();
    int off = (out_size > SEQ) ? (out_size - SEQ) : 0;
    for (int idx = tid; idx < VCHK; idx += blockDim.x)
        out[off + a + idx] = (float)ys[idx];
}

// ---------------- launch ----------------
extern "C" void kernel_launch(void* const* d_in, const int* in_sizes, int n_in,
                              void* d_out, int out_size)
{
    const int*   sent  = (const int*)d_in[0];
    const float* embed = (const float*)d_in[1];
    const float* wihf  = (const float*)d_in[2];
    const float* whhf  = (const float*)d_in[3];
    const float* bihf  = (const float*)d_in[4];
    const float* bhhf  = (const float*)d_in[5];
    const float* wihb  = (const float*)d_in[6];
    const float* whhb  = (const float*)d_in[7];
    const float* bihb  = (const float*)d_in[8];
    const float* bhhb  = (const float*)d_in[9];
    const float* h0    = (const float*)d_in[10];
    const float* c0    = (const float*)d_in[11];
    const float* wtag  = (const float*)d_in[12];
    const float* btag  = (const float*)d_in[13];
    const float* trans = (const float*)d_in[14];
    float* out = (float*)d_out;

    cudaFuncSetAttribute(k_vitfv, cudaFuncAttributeMaxDynamicSharedMemorySize, VIT_SMEM_BYTES);

    // 1) embedding + input projections
    k_embed_proj<<<SEQ / TOKB, TPB_E>>>(sent, embed, wihf, bihf, bhhf, wihb, bihb, bhhb);

    // 1b) no-op shims: keep k_lstm in the ncu-profiled launch slot
    k_nop1<<<1, 32>>>();
    k_nop2<<<1, 32>>>();

    // 2) chunked BiLSTM: 18 clusters of 8 CTAs, 4 chunk-streams per cluster
    {
        cudaLaunchConfig_t cfg = {};
        cfg.gridDim = dim3(144, 1, 1);
        cfg.blockDim = dim3(TPB_L, 1, 1);
        cfg.dynamicSmemBytes = 0;
        cfg.stream = 0;
        cudaLaunchAttribute attrs[1];
        attrs[0].id = cudaLaunchAttributeClusterDimension;
        attrs[0].val.clusterDim.x = 8;
        attrs[0].val.clusterDim.y = 1;
        attrs[0].val.clusterDim.z = 1;
        cfg.attrs = attrs;
        cfg.numAttrs = 1;
        cudaLaunchKernelEx(&cfg, k_lstm, whhf, whhb, h0, c0);
    }

    // 3) tag projection (8 tokens/block)
    k_feats<<<SEQ / FTOK, 640>>>(wtag, btag);

    // 4) serial fv recurrence (stores fv trajectory + best + score)
    k_vitfv<<<1, 256, VIT_SMEM_BYTES>>>(trans, out, out_size);

    // 4b) parallel, bitwise-exact backpointers from the fv trajectory
    k_bp<<<SEQ / BPT, BPT * NTAG>>>(trans);

    // 5) exact parallel backtrace: chunk maps -> chain -> emit
    k_map<<<VNC, 128>>>();
    k_chain<<<1, 32>>>();
    k_emit<<<VNC, 128>>>(out, out_size);
}